// round 16
// baseline (speedup 1.0000x reference)
#include <cuda_runtime.h>
#include <cuda_fp16.h>
#include <math.h>
#include <stdint.h>

// Problem dims
#define B_   4
#define LQ_  1024
#define LKV_ 2048
#define D_   1024
#define H_   16
#define HD_  64

// ================= warp-MMA helpers (baseline PTX, sm_80+) =================
__device__ __forceinline__ uint32_t smem_to_u32(const void* p) {
    uint32_t a;
    asm("{ .reg .u64 t; cvta.to.shared.u64 t, %1; cvt.u32.u64 %0, t; }"
        : "=r"(a) : "l"(p));
    return a;
}
__device__ __forceinline__ void ldmatrix_x4(uint32_t* r, uint32_t addr) {
    asm volatile("ldmatrix.sync.aligned.m8n8.x4.shared.b16 {%0,%1,%2,%3}, [%4];"
        : "=r"(r[0]), "=r"(r[1]), "=r"(r[2]), "=r"(r[3]) : "r"(addr));
}
__device__ __forceinline__ void ldmatrix_x4_trans(uint32_t* r, uint32_t addr) {
    asm volatile("ldmatrix.sync.aligned.m8n8.x4.trans.shared.b16 {%0,%1,%2,%3}, [%4];"
        : "=r"(r[0]), "=r"(r[1]), "=r"(r[2]), "=r"(r[3]) : "r"(addr));
}
// fp32-accumulate MMA (attention)
__device__ __forceinline__ void mma_16816(float* d, const uint32_t* a,
                                          uint32_t b0, uint32_t b1) {
    asm volatile("mma.sync.aligned.m16n8k16.row.col.f32.f16.f16.f32 "
        "{%0,%1,%2,%3}, {%4,%5,%6,%7}, {%8,%9}, {%0,%1,%2,%3};"
        : "+f"(d[0]), "+f"(d[1]), "+f"(d[2]), "+f"(d[3])
        : "r"(a[0]), "r"(a[1]), "r"(a[2]), "r"(a[3]), "r"(b0), "r"(b1));
}
// fp16-accumulate MMA (projection GEMMs, 2x rate)
__device__ __forceinline__ void mma_16816_h(uint32_t* d, const uint32_t* a,
                                            uint32_t b0, uint32_t b1) {
    asm volatile("mma.sync.aligned.m16n8k16.row.col.f16.f16.f16.f16 "
        "{%0,%1}, {%2,%3,%4,%5}, {%6,%7}, {%0,%1};"
        : "+r"(d[0]), "+r"(d[1])
        : "r"(a[0]), "r"(a[1]), "r"(a[2]), "r"(a[3]), "r"(b0), "r"(b1));
}
__device__ __forceinline__ void cp_async16(uint32_t smem_addr, const void* gptr) {
    asm volatile("cp.async.cg.shared.global [%0], [%1], 16;"
        :: "r"(smem_addr), "l"(gptr));
}
#define CP_ASYNC_COMMIT() asm volatile("cp.async.commit_group;" ::: "memory")
#define CP_ASYNC_WAIT(N)  asm volatile("cp.async.wait_group %0;" :: "n"(N) : "memory")

// ================= scratch =================
__device__ __half g_qk  [B_ * LQ_  * D_];
__device__ __half g_kvk [B_ * LKV_ * D_];
__device__ __half g_ak  [B_ * LQ_  * D_];
__device__ __half g_wq  [D_ * D_];
__device__ __half g_wkv [2 * D_ * D_];
__device__ __half g_wo  [D_ * D_];
__device__ __half g_q1 [B_ * H_ * LQ_  * HD_];
__device__ __half g_k1 [B_ * H_ * LKV_ * HD_];
__device__ __half g_v1 [B_ * H_ * LKV_ * HD_];
__device__ int g_len[B_];

// ================= fused prep: lengths | weight-convert | layernorm =================
#define PREP_W0 1
#define PREP_LN0 (PREP_W0 + (4 * D_ * D_) / 1024)     // 4097
#define PREP_BLOCKS (PREP_LN0 + B_ * (LQ_ + LKV_))    // 16385

__global__ void __launch_bounds__(256) prep_kernel(
    const unsigned char* __restrict__ mask,
    const float* __restrict__ Wq, const float* __restrict__ Wkv,
    const float* __restrict__ Wo,
    __half* __restrict__ wq, __half* __restrict__ wkv, __half* __restrict__ wo,
    const float* __restrict__ xq, const float* __restrict__ xkv,
    const float* __restrict__ nqw, const float* __restrict__ nqb,
    const float* __restrict__ nkw, const float* __restrict__ nkb,
    __half* __restrict__ yq, __half* __restrict__ ykv)
{
    const int bid = blockIdx.x;
    const int tid = threadIdx.x;

    if (bid == 0) {
        __shared__ int det[4];
        __shared__ int cnt[4];
        __shared__ int mode;
        if (tid < 4) { det[tid] = 0; cnt[tid] = 0; }
        __syncthreads();
        for (int i = tid; i < B_ * LKV_; i += blockDim.x)
            if (mask[i]) atomicOr(&det[i & 3], 1);
        __syncthreads();
        if (tid == 0) {
            if (det[1])                mode = 0;
            else if (det[2] || det[3]) mode = det[0] ? 0 : 2;
            else if (det[0])           mode = 1;
            else                       mode = 0;
        }
        __syncthreads();
        int md = mode;
        for (int b = 0; b < B_; b++) {
            int local = 0;
            for (int k = tid; k < LKV_; k += blockDim.x) {
                int idx = b * LKV_ + k;
                bool t;
                if      (md == 0) t = mask[idx] != 0;
                else if (md == 1) t = ((const int*)  mask)[idx] != 0;
                else              t = ((const float*)mask)[idx] != 0.0f;
                if (!t) local++;
            }
            atomicAdd(&cnt[b], local);
        }
        __syncthreads();
        if (tid < B_) g_len[tid] = cnt[tid];
        return;
    }

    if (bid < PREP_LN0) {
        int idx4 = ((bid - PREP_W0) * 256 + tid) * 4;
        const float* src;
        __half* dst;
        if (idx4 < D_ * D_)          { src = Wq;  dst = wq;  }
        else if (idx4 < 3 * D_ * D_) { src = Wkv; dst = wkv; idx4 -= D_ * D_; }
        else                         { src = Wo;  dst = wo;  idx4 -= 3 * D_ * D_; }
        float4 v = *(const float4*)(src + idx4);
        *(__half2*)(dst + idx4)     = __floats2half2_rn(v.x, v.y);
        *(__half2*)(dst + idx4 + 2) = __floats2half2_rn(v.z, v.w);
        return;
    }

    {
        int r = bid - PREP_LN0;
        const bool is_q = (r < B_ * LQ_);
        const int  row  = is_q ? r : r - B_ * LQ_;
        const float* x  = is_q ? xq  : xkv;
        const float* w  = is_q ? nqw : nkw;
        const float* bb = is_q ? nqb : nkb;
        __half* y       = is_q ? yq  : ykv;

        const float* xr = x + (size_t)row * D_;
        float4 v = *(const float4*)(xr + tid * 4);
        float s  = v.x + v.y + v.z + v.w;
        float sq = v.x * v.x + v.y * v.y + v.z * v.z + v.w * v.w;
        #pragma unroll
        for (int o = 16; o; o >>= 1) {
            s  += __shfl_xor_sync(0xffffffffu, s,  o);
            sq += __shfl_xor_sync(0xffffffffu, sq, o);
        }
        __shared__ float ss[8], ssq[8];
        int wid = tid >> 5, ln = tid & 31;
        if (ln == 0) { ss[wid] = s; ssq[wid] = sq; }
        __syncthreads();
        if (tid == 0) {
            float S = 0.f, SQ = 0.f;
            #pragma unroll
            for (int i = 0; i < 8; i++) { S += ss[i]; SQ += ssq[i]; }
            float mu  = S * (1.0f / D_);
            float var = SQ * (1.0f / D_) - mu * mu;
            ss[0]  = mu;
            ssq[0] = rsqrtf(fmaxf(var, 0.0f) + 1e-5f);
        }
        __syncthreads();
        float mu = ss[0], inv = ssq[0];
        float4 wv = *(const float4*)(w  + tid * 4);
        float4 bv = *(const float4*)(bb + tid * 4);
        __half* yr = y + (size_t)row * D_ + tid * 4;
        *(__half2*)(yr)     = __floats2half2_rn((v.x - mu) * inv * wv.x + bv.x,
                                                (v.y - mu) * inv * wv.y + bv.y);
        *(__half2*)(yr + 2) = __floats2half2_rn((v.z - mu) * inv * wv.z + bv.z,
                                                (v.w - mu) * inv * wv.w + bv.w);
    }
}

// ========== per-head write helpers for GEMM epilogues ==========
__device__ __forceinline__ void write_q_pair(int mrow, int n, float2 v) {
    int b = mrow >> 10, qr = mrow & 1023, h = n >> 6, d = n & 63;
    __half* dst = g_q1 + ((size_t)((b * H_ + h) * LQ_ + qr)) * HD_ + d;
    *(__half2*)dst = __floats2half2_rn(v.x, v.y);
}
__device__ __forceinline__ void write_kv_pair(int mrow, int n, float2 v) {
    int b = mrow >> 11, kr = mrow & 2047;
    int h2 = n >> 6, d = n & 63;
    __half* dst = (h2 < H_)
        ? g_k1 + ((size_t)((b * H_ + h2) * LKV_ + kr)) * HD_ + d
        : g_v1 + ((size_t)((b * H_ + (h2 - H_)) * LKV_ + kr)) * HD_ + d;
    *(__half2*)dst = __floats2half2_rn(v.x, v.y);
}

// ====== fp16-acc GEMM: 64x128 CTA tile, 4 warps (warp 32x64), BK=32, NK=32 ======
// fp16 accumulate over K=64 windows (4 chained k16-MMAs), promoted to fp32.
// MODE 0: fp32 C + bias + residual; MODE 1: Q per-head; MODE 2: KV per-head.
#define SSTRIDE 40                       // fp16 per smem row (80B)
#define ASTAGE_B (64  * SSTRIDE * 2)     // 5120 B
#define BSTAGE_B (128 * SSTRIDE * 2)     // 10240 B
#define GSTAGES 3
#define GEMM_SMEM (GSTAGES * (ASTAGE_B + BSTAGE_B))   // 46080 B
#define NKG (D_ / 32)   // 32

template <int MODE>
__device__ __forceinline__ void gemm_body(
    const __half* __restrict__ A, const __half* __restrict__ W,
    const float* __restrict__ bias, const float* __restrict__ R,
    float* __restrict__ C, int N, int m0, int n0, char* gsm)
{
    const uint32_t smem_u = smem_to_u32(gsm);
    const uint32_t sa_u = smem_u;                        // A stages 0..2
    const uint32_t sb_u = smem_u + GSTAGES * ASTAGE_B;   // B stages 0..2

    const int tid  = threadIdx.x;       // 0..127
    const int lane = tid & 31;
    const int wid  = tid >> 5;          // 0..3
    const int warp_m = wid & 1;
    const int warp_n = wid >> 1;

    const int lr = tid >> 2;            // 0..31
    const int lu = tid & 3;             // 16B unit within 64B row
    const uint32_t row_b = (uint32_t)(lr * SSTRIDE * 2 + lu * 16);

    float acc[2][8][4];
    #pragma unroll
    for (int i = 0; i < 2; i++)
        #pragma unroll
        for (int j = 0; j < 8; j++)
            #pragma unroll
            for (int t = 0; t < 4; t++) acc[i][j][t] = 0.0f;

    const uint32_t a_off = (uint32_t)((warp_m * 32 + (lane & 15)) * SSTRIDE * 2
                                      + (lane >> 4) * 16);
    const uint32_t b_off = (uint32_t)((warp_n * 64 + ((lane >> 4) & 1) * 8 + (lane & 7)) * SSTRIDE * 2
                                      + ((lane >> 3) & 1) * 16);

    auto issue_stage = [&](int kt, int buf) {
        const size_t koff = (size_t)kt * 32;
        const uint32_t sa_s = sa_u + (uint32_t)(buf * ASTAGE_B);
        const uint32_t sb_s = sb_u + (uint32_t)(buf * BSTAGE_B);
        // A: 64 rows x 4 units = 256 units, 2 per thread
        cp_async16(sa_s + row_b, A + (size_t)(m0 + lr) * D_ + koff + lu * 8);
        cp_async16(sa_s + row_b + (uint32_t)(32 * SSTRIDE * 2),
                   A + (size_t)(m0 + 32 + lr) * D_ + koff + lu * 8);
        // B: 128 rows x 4 units = 512 units, 4 per thread
        #pragma unroll
        for (int rep = 0; rep < 4; rep++) {
            cp_async16(sb_s + row_b + (uint32_t)(rep * 32 * SSTRIDE * 2),
                       W + (size_t)(n0 + rep * 32 + lr) * D_ + koff + lu * 8);
        }
    };

    issue_stage(0, 0);
    CP_ASYNC_COMMIT();

    for (int kt2 = 0; kt2 < NKG / 2; kt2++) {
        uint32_t acch[2][8][2];
        #pragma unroll
        for (int i = 0; i < 2; i++)
            #pragma unroll
            for (int j = 0; j < 8; j++) { acch[i][j][0] = 0u; acch[i][j][1] = 0u; }

        #pragma unroll
        for (int sub = 0; sub < 2; sub++) {
            const int kt = kt2 * 2 + sub;
            if (kt + 1 < NKG) issue_stage(kt + 1, (kt + 1) % 3);
            CP_ASYNC_COMMIT();
            CP_ASYNC_WAIT(1);
            __syncthreads();

            const int cur = kt % 3;
            const uint32_t sa_cur = sa_u + (uint32_t)(cur * ASTAGE_B);
            const uint32_t sb_cur = sb_u + (uint32_t)(cur * BSTAGE_B);
            #pragma unroll
            for (int ks = 0; ks < 2; ks++) {
                uint32_t a_frag[2][4];
                #pragma unroll
                for (int im = 0; im < 2; im++)
                    ldmatrix_x4(a_frag[im], sa_cur + a_off
                                + (uint32_t)((im * 16 + warp_m * 0) * SSTRIDE * 2 + ks * 32));
                uint32_t b_frag[4][4];
                #pragma unroll
                for (int iu = 0; iu < 4; iu++)
                    ldmatrix_x4(b_frag[iu], sb_cur + b_off
                                + (uint32_t)(iu * 16 * SSTRIDE * 2 + ks * 32));
                #pragma unroll
                for (int im = 0; im < 2; im++)
                    #pragma unroll
                    for (int iu = 0; iu < 4; iu++) {
                        mma_16816_h(acch[im][iu * 2 + 0], a_frag[im], b_frag[iu][0], b_frag[iu][1]);
                        mma_16816_h(acch[im][iu * 2 + 1], a_frag[im], b_frag[iu][2], b_frag[iu][3]);
                    }
            }
        }

        // promote K=64 window into fp32 master accumulators
        #pragma unroll
        for (int im = 0; im < 2; im++)
            #pragma unroll
            for (int in = 0; in < 8; in++) {
                float2 f0 = __half22float2(*(__half2*)&acch[im][in][0]);
                float2 f1 = __half22float2(*(__half2*)&acch[im][in][1]);
                acc[im][in][0] += f0.x;
                acc[im][in][1] += f0.y;
                acc[im][in][2] += f1.x;
                acc[im][in][3] += f1.y;
            }
    }

    const int gr = lane >> 2;
    const int gc = (lane & 3) * 2;
    #pragma unroll
    for (int im = 0; im < 2; im++) {
        const int mrow = m0 + warp_m * 32 + im * 16 + gr;
        #pragma unroll
        for (int in = 0; in < 8; in++) {
            const int n = n0 + warp_n * 64 + in * 8 + gc;
            float b0 = bias[n], b1 = bias[n + 1];
            float2 v0 = make_float2(acc[im][in][0] + b0, acc[im][in][1] + b1);
            float2 v1 = make_float2(acc[im][in][2] + b0, acc[im][in][3] + b1);
            if (MODE == 0) {
                float2 r0 = *(const float2*)(R + (size_t)mrow * N + n);
                float2 r1 = *(const float2*)(R + (size_t)(mrow + 8) * N + n);
                v0.x += r0.x; v0.y += r0.y;
                v1.x += r1.x; v1.y += r1.y;
                *(float2*)(C + (size_t)mrow * N + n)       = v0;
                *(float2*)(C + (size_t)(mrow + 8) * N + n) = v1;
            } else if (MODE == 1) {
                write_q_pair(mrow,     n, v0);
                write_q_pair(mrow + 8, n, v1);
            } else {
                write_kv_pair(mrow,     n, v0);
                write_kv_pair(mrow + 8, n, v1);
            }
        }
    }
}

// fused Q+KV projection: blocks [0,2048) = KV tiles (64x128), [2048,2560) = Q.
__global__ void __launch_bounds__(128, 3) proj_qkv_kernel(
    const __half* __restrict__ qk, const __half* __restrict__ kvk,
    const __half* __restrict__ wq, const __half* __restrict__ wkv,
    const float* __restrict__ bq, const float* __restrict__ bkv)
{
    extern __shared__ char gsm[];
    const int bid = blockIdx.x;
    if (bid < 2048) {
        const int m0 = (bid >> 4) * 64, n0 = (bid & 15) * 128;
        const int b = m0 >> 11, kr0 = m0 & 2047;
        if (kr0 >= g_len[b]) return;   // attention never reads these kv rows
        gemm_body<2>(kvk, wkv, bkv, nullptr, nullptr, 2 * D_, m0, n0, gsm);
    } else {
        const int r = bid - 2048;
        const int m0 = (r >> 3) * 64, n0 = (r & 7) * 128;
        gemm_body<1>(qk, wq, bq, nullptr, nullptr, D_, m0, n0, gsm);
    }
}

// O projection + residual
__global__ void __launch_bounds__(128, 3) proj_o_kernel(
    const __half* __restrict__ ak, const __half* __restrict__ wo,
    const float* __restrict__ bo, const float* __restrict__ R,
    float* __restrict__ out)
{
    extern __shared__ char gsm[];
    const int bid = blockIdx.x;
    const int m0 = (bid >> 3) * 64, n0 = (bid & 7) * 128;
    gemm_body<0>(ak, wo, bo, R, out, D_, m0, n0, gsm);
}

// ================= fp16 HMMA flash attention (unchanged from R14) =================
#define AQ  128
#define SQ  72
#define KTILE 4608
#define FA_SMEM_BYTES ((27648 + 9216) * 2)   // 73728

__global__ void __launch_bounds__(256, 2) flash_attn_mma_kernel(
    const __half* __restrict__ q1, const __half* __restrict__ k1,
    const __half* __restrict__ v1, __half* __restrict__ outk)
{
    extern __shared__ __half smem_h[];
    __half* Qs = smem_h + 27648;

    const int b = blockIdx.z, h = blockIdx.y, qt = blockIdx.x;
    const int tid = threadIdx.x, lane = tid & 31, wid = tid >> 5;
    const int gr = lane >> 2, gc = (lane & 3) * 2;

    const uint32_t smem_u = smem_to_u32(smem_h);
    const uint32_t ks_u = smem_u;
    const uint32_t vs_u = smem_u + 3 * KTILE * 2;
    const uint32_t qs_u = smem_u + 27648 * 2;

    const __half* qg = q1 + ((size_t)((b * H_ + h) * LQ_ + qt * AQ)) * HD_;
    #pragma unroll
    for (int rep = 0; rep < 4; rep++) {
        int idx = rep * 256 + tid;
        int r = idx >> 3, u = idx & 7;
        *(uint4*)&Qs[r * SQ + u * 8] = *(const uint4*)(qg + (size_t)r * HD_ + u * 8);
    }
    __syncthreads();

    uint32_t qfrag[4][4];
    const uint32_t a_base = qs_u + (uint32_t)((wid * 16 + (lane & 15)) * SQ * 2
                                              + (lane >> 4) * 16);
    #pragma unroll
    for (int ks = 0; ks < 4; ks++)
        ldmatrix_x4(qfrag[ks], a_base + (uint32_t)(ks * 32));

    const uint32_t kb_off = (uint32_t)((((lane >> 4) & 1) * 8 + (lane & 7)) * SQ * 2
                                       + ((lane >> 3) & 1) * 16);
    const uint32_t vb_off = (uint32_t)(((lane & 7) + ((lane >> 3) & 1) * 8) * SQ * 2
                                       + (lane >> 4) * 16);

    const int len   = g_len[b];
    const int ntile = (len + 63) >> 6;

    const __half* kbase = k1 + ((size_t)((b * H_ + h) * LKV_)) * HD_;
    const __half* vbase = v1 + ((size_t)((b * H_ + h) * LKV_)) * HD_;

    auto issue_tile = [&](int kt, int buf) {
        const __half* kg = kbase + (size_t)(kt * 64) * HD_;
        const __half* vg = vbase + (size_t)(kt * 64) * HD_;
        const uint32_t kdst = ks_u + (uint32_t)(buf * KTILE * 2);
        const uint32_t vdst = vs_u + (uint32_t)(buf * KTILE * 2);
        #pragma unroll
        for (int rep = 0; rep < 2; rep++) {
            int idx = rep * 256 + tid;
            int r = idx >> 3, u = idx & 7;
            uint32_t off = (uint32_t)((r * SQ + u * 8) * 2);
            cp_async16(kdst + off, kg + (size_t)r * HD_ + u * 8);
            cp_async16(vdst + off, vg + (size_t)r * HD_ + u * 8);
        }
    };

    float m_r[2] = {-1e30f, -1e30f};
    float l_r[2] = {0.0f, 0.0f};
    float acc_o[8][4];
    #pragma unroll
    for (int i = 0; i < 8; i++)
        #pragma unroll
        for (int j = 0; j < 4; j++) acc_o[i][j] = 0.0f;

    issue_tile(0, 0);
    CP_ASYNC_COMMIT();

    for (int kt = 0; kt < ntile; kt++) {
        const int buf = kt % 3;
        if (kt + 1 < ntile) issue_tile(kt + 1, (kt + 1) % 3);
        CP_ASYNC_COMMIT();
        CP_ASYNC_WAIT(1);
        __syncthreads();

        const uint32_t kcur = ks_u + (uint32_t)(buf * KTILE * 2);
        const uint32_t vcur = vs_u + (uint32_t)(buf * KTILE * 2);

        float acc_s[8][4];
        #pragma unroll
        for (int i = 0; i < 8; i++)
            #pragma unroll
            for (int j = 0; j < 4; j++) acc_s[i][j] = 0.0f;

        #pragma unroll
        for (int ks = 0; ks < 4; ks++) {
            uint32_t bf[4][4];
            #pragma unroll
            for (int nt4 = 0; nt4 < 4; nt4++)
                ldmatrix_x4(bf[nt4], kcur + kb_off
                            + (uint32_t)(nt4 * 16 * SQ * 2 + ks * 32));
            #pragma unroll
            for (int nt4 = 0; nt4 < 4; nt4++) {
                mma_16816(acc_s[nt4 * 2 + 0], qfrag[ks], bf[nt4][0], bf[nt4][1]);
                mma_16816(acc_s[nt4 * 2 + 1], qfrag[ks], bf[nt4][2], bf[nt4][3]);
            }
        }

        const int rem = len - kt * 64;
        #pragma unroll
        for (int nt = 0; nt < 8; nt++) {
            int c0 = nt * 8 + gc;
            bool k0 = (c0 >= rem), k1m = (c0 + 1 >= rem);
            acc_s[nt][0] = k0  ? -1e9f : acc_s[nt][0] * 0.125f;
            acc_s[nt][1] = k1m ? -1e9f : acc_s[nt][1] * 0.125f;
            acc_s[nt][2] = k0  ? -1e9f : acc_s[nt][2] * 0.125f;
            acc_s[nt][3] = k1m ? -1e9f : acc_s[nt][3] * 0.125f;
        }

        float tmax0 = -1e30f, tmax1 = -1e30f;
        #pragma unroll
        for (int nt = 0; nt < 8; nt++) {
            tmax0 = fmaxf(tmax0, fmaxf(acc_s[nt][0], acc_s[nt][1]));
            tmax1 = fmaxf(tmax1, fmaxf(acc_s[nt][2], acc_s[nt][3]));
        }
        #pragma unroll
        for (int o = 1; o < 4; o <<= 1) {
            tmax0 = fmaxf(tmax0, __shfl_xor_sync(0xffffffffu, tmax0, o));
            tmax1 = fmaxf(tmax1, __shfl_xor_sync(0xffffffffu, tmax1, o));
        }
        float mn0 = fmaxf(m_r[0], tmax0), mn1 = fmaxf(m_r[1], tmax1);
        float al0 = __expf(m_r[0] - mn0), al1 = __expf(m_r[1] - mn1);
        float rs0 = 0.0f, rs1 = 0.0f;
        #pragma unroll
        for (int nt = 0; nt < 8; nt++) {
            acc_s[nt][0] = __expf(acc_s[nt][0] - mn0);
            acc_s[nt][1] = __expf(acc_s[nt][1] - mn0);
            acc_s[nt][2] = __expf(acc_s[nt][2] - mn1);
            acc_s[nt][3] = __expf(acc_s[nt][3] - mn1);
            rs0 += acc_s[nt][0] + acc_s[nt][1];
            rs1 += acc_s[nt][2] + acc_s[nt][3];
        }
        #pragma unroll
        for (int o = 1; o < 4; o <<= 1) {
            rs0 += __shfl_xor_sync(0xffffffffu, rs0, o);
            rs1 += __shfl_xor_sync(0xffffffffu, rs1, o);
        }
        l_r[0] = l_r[0] * al0 + rs0;  m_r[0] = mn0;
        l_r[1] = l_r[1] * al1 + rs1;  m_r[1] = mn1;
        #pragma unroll
        for (int nt = 0; nt < 8; nt++) {
            acc_o[nt][0] *= al0; acc_o[nt][1] *= al0;
            acc_o[nt][2] *= al1; acc_o[nt][3] *= al1;
        }

        #pragma unroll
        for (int ks4 = 0; ks4 < 4; ks4++) {
            uint32_t af[4];
            __half2 t0 = __floats2half2_rn(acc_s[2 * ks4][0],     acc_s[2 * ks4][1]);
            __half2 t1 = __floats2half2_rn(acc_s[2 * ks4][2],     acc_s[2 * ks4][3]);
            __half2 t2 = __floats2half2_rn(acc_s[2 * ks4 + 1][0], acc_s[2 * ks4 + 1][1]);
            __half2 t3 = __floats2half2_rn(acc_s[2 * ks4 + 1][2], acc_s[2 * ks4 + 1][3]);
            af[0] = *(uint32_t*)&t0;
            af[1] = *(uint32_t*)&t1;
            af[2] = *(uint32_t*)&t2;
            af[3] = *(uint32_t*)&t3;
            uint32_t bf[4][4];
            #pragma unroll
            for (int g = 0; g < 4; g++)
                ldmatrix_x4_trans(bf[g], vcur + vb_off
                                  + (uint32_t)(ks4 * 16 * SQ * 2 + g * 32));
            #pragma unroll
            for (int g = 0; g < 4; g++) {
                mma_16816(acc_o[g * 2 + 0], af, bf[g][0], bf[g][1]);
                mma_16816(acc_o[g * 2 + 1], af, bf[g][2], bf[g][3]);
            }
        }
    }

    float inv0 = 1.0f / l_r[0], inv1 = 1.0f / l_r[1];
    const int qrow0 = qt * AQ + wid * 16 + gr;
    __half* p0 = outk + ((size_t)(b * LQ_ + qrow0)) * D_ + h * HD_;
    __half* p1 = p0 + (size_t)8 * D_;
    #pragma unroll
    for (int nt = 0; nt < 8; nt++) {
        int col = nt * 8 + gc;
        *(__half2*)(p0 + col) = __floats2half2_rn(acc_o[nt][0] * inv0,
                                                  acc_o[nt][1] * inv0);
        *(__half2*)(p1 + col) = __floats2half2_rn(acc_o[nt][2] * inv1,
                                                  acc_o[nt][3] * inv1);
    }
}

// ================= host launcher =================
extern "C" void kernel_launch(void* const* d_in, const int* in_sizes, int n_in,
                              void* d_out, int out_size) {
    const float*         q    = (const float*)d_in[0];
    const float*         kv   = (const float*)d_in[1];
    const unsigned char* mask = (const unsigned char*)d_in[2];
    const float*         nqw  = (const float*)d_in[3];
    const float*         nqb  = (const float*)d_in[4];
    const float*         nkw  = (const float*)d_in[5];
    const float*         nkb  = (const float*)d_in[6];
    const float*         Wq   = (const float*)d_in[7];
    const float*         bq   = (const float*)d_in[8];
    const float*         Wkv  = (const float*)d_in[9];
    const float*         bkv  = (const float*)d_in[10];
    const float*         Wo   = (const float*)d_in[11];
    const float*         bo   = (const float*)d_in[12];
    float* out = (float*)d_out;

    __half *qk, *kvk, *ak, *wq, *wkv, *wo, *q1, *k1, *v1;
    cudaGetSymbolAddress((void**)&qk,  g_qk);
    cudaGetSymbolAddress((void**)&kvk, g_kvk);
    cudaGetSymbolAddress((void**)&ak,  g_ak);
    cudaGetSymbolAddress((void**)&wq,  g_wq);
    cudaGetSymbolAddress((void**)&wkv, g_wkv);
    cudaGetSymbolAddress((void**)&wo,  g_wo);
    cudaGetSymbolAddress((void**)&q1,  g_q1);
    cudaGetSymbolAddress((void**)&k1,  g_k1);
    cudaGetSymbolAddress((void**)&v1,  g_v1);

    cudaFuncSetAttribute(flash_attn_mma_kernel,
                         cudaFuncAttributeMaxDynamicSharedMemorySize, FA_SMEM_BYTES);
    cudaFuncSetAttribute(proj_qkv_kernel,
                         cudaFuncAttributeMaxDynamicSharedMemorySize, GEMM_SMEM);
    cudaFuncSetAttribute(proj_o_kernel,
                         cudaFuncAttributeMaxDynamicSharedMemorySize, GEMM_SMEM);

    prep_kernel<<<PREP_BLOCKS, 256>>>(mask, Wq, Wkv, Wo, wq, wkv, wo,
                                      q, kv, nqw, nqb, nkw, nkb, qk, kvk); // 0

    proj_qkv_kernel<<<2560, 128, GEMM_SMEM>>>(qk, kvk, wq, wkv, bq, bkv);  // 1

    flash_attn_mma_kernel<<<dim3(LQ_ / AQ, H_, B_), 256, FA_SMEM_BYTES>>>(
        q1, k1, v1, ak);                                                    // 2

    proj_o_kernel<<<512, 128, GEMM_SMEM>>>(ak, wo, bo, q, out);             // 3
}

// round 17
// speedup vs baseline: 1.1579x; 1.1579x over previous
#include <cuda_runtime.h>
#include <cuda_fp16.h>
#include <math.h>
#include <stdint.h>

// Problem dims
#define B_   4
#define LQ_  1024
#define LKV_ 2048
#define D_   1024
#define H_   16
#define HD_  64

// ================= warp-MMA helpers (baseline PTX, sm_80+) =================
__device__ __forceinline__ uint32_t smem_to_u32(const void* p) {
    uint32_t a;
    asm("{ .reg .u64 t; cvta.to.shared.u64 t, %1; cvt.u32.u64 %0, t; }"
        : "=r"(a) : "l"(p));
    return a;
}
__device__ __forceinline__ void ldmatrix_x4(uint32_t* r, uint32_t addr) {
    asm volatile("ldmatrix.sync.aligned.m8n8.x4.shared.b16 {%0,%1,%2,%3}, [%4];"
        : "=r"(r[0]), "=r"(r[1]), "=r"(r[2]), "=r"(r[3]) : "r"(addr));
}
__device__ __forceinline__ void ldmatrix_x4_trans(uint32_t* r, uint32_t addr) {
    asm volatile("ldmatrix.sync.aligned.m8n8.x4.trans.shared.b16 {%0,%1,%2,%3}, [%4];"
        : "=r"(r[0]), "=r"(r[1]), "=r"(r[2]), "=r"(r[3]) : "r"(addr));
}
__device__ __forceinline__ void mma_16816(float* d, const uint32_t* a,
                                          uint32_t b0, uint32_t b1) {
    asm volatile("mma.sync.aligned.m16n8k16.row.col.f32.f16.f16.f32 "
        "{%0,%1,%2,%3}, {%4,%5,%6,%7}, {%8,%9}, {%0,%1,%2,%3};"
        : "+f"(d[0]), "+f"(d[1]), "+f"(d[2]), "+f"(d[3])
        : "r"(a[0]), "r"(a[1]), "r"(a[2]), "r"(a[3]), "r"(b0), "r"(b1));
}
__device__ __forceinline__ void cp_async16(uint32_t smem_addr, const void* gptr) {
    asm volatile("cp.async.cg.shared.global [%0], [%1], 16;"
        :: "r"(smem_addr), "l"(gptr));
}
#define CP_ASYNC_COMMIT() asm volatile("cp.async.commit_group;" ::: "memory")
#define CP_ASYNC_WAIT(N)  asm volatile("cp.async.wait_group %0;" :: "n"(N) : "memory")

// ================= scratch =================
__device__ __half g_qk  [B_ * LQ_  * D_];        // LN(q)  fp16 (GEMM A)
__device__ __half g_kvk [B_ * LKV_ * D_];        // LN(kv) fp16 (GEMM A)
__device__ __half g_ak  [B_ * LQ_  * D_];        // attn out fp16 (GEMM A)
__device__ __half g_wq  [D_ * D_];
__device__ __half g_wkv [2 * D_ * D_];
__device__ __half g_wo  [D_ * D_];
__device__ __half g_q1 [B_ * H_ * LQ_  * HD_];   // Q per head
__device__ __half g_k1 [B_ * H_ * LKV_ * HD_];   // K per head
__device__ __half g_v1 [B_ * H_ * LKV_ * HD_];   // V per head
__device__ int g_len[B_];

// ================= fused prep: lengths | weight-convert | layernorm =================
#define PREP_W0 1
#define PREP_LN0 (PREP_W0 + (4 * D_ * D_) / 1024)     // 4097
#define PREP_BLOCKS (PREP_LN0 + B_ * (LQ_ + LKV_))    // 16385

__global__ void __launch_bounds__(256) prep_kernel(
    const unsigned char* __restrict__ mask,
    const float* __restrict__ Wq, const float* __restrict__ Wkv,
    const float* __restrict__ Wo,
    __half* __restrict__ wq, __half* __restrict__ wkv, __half* __restrict__ wo,
    const float* __restrict__ xq, const float* __restrict__ xkv,
    const float* __restrict__ nqw, const float* __restrict__ nqb,
    const float* __restrict__ nkw, const float* __restrict__ nkb,
    __half* __restrict__ yq, __half* __restrict__ ykv)
{
    const int bid = blockIdx.x;
    const int tid = threadIdx.x;

    if (bid == 0) {
        __shared__ int det[4];
        __shared__ int cnt[4];
        __shared__ int mode;
        if (tid < 4) { det[tid] = 0; cnt[tid] = 0; }
        __syncthreads();
        for (int i = tid; i < B_ * LKV_; i += blockDim.x)
            if (mask[i]) atomicOr(&det[i & 3], 1);
        __syncthreads();
        if (tid == 0) {
            if (det[1])                mode = 0;
            else if (det[2] || det[3]) mode = det[0] ? 0 : 2;
            else if (det[0])           mode = 1;
            else                       mode = 0;
        }
        __syncthreads();
        int md = mode;
        for (int b = 0; b < B_; b++) {
            int local = 0;
            for (int k = tid; k < LKV_; k += blockDim.x) {
                int idx = b * LKV_ + k;
                bool t;
                if      (md == 0) t = mask[idx] != 0;
                else if (md == 1) t = ((const int*)  mask)[idx] != 0;
                else              t = ((const float*)mask)[idx] != 0.0f;
                if (!t) local++;
            }
            atomicAdd(&cnt[b], local);
        }
        __syncthreads();
        if (tid < B_) g_len[tid] = cnt[tid];
        return;
    }

    if (bid < PREP_LN0) {
        int idx4 = ((bid - PREP_W0) * 256 + tid) * 4;
        const float* src;
        __half* dst;
        if (idx4 < D_ * D_)          { src = Wq;  dst = wq;  }
        else if (idx4 < 3 * D_ * D_) { src = Wkv; dst = wkv; idx4 -= D_ * D_; }
        else                         { src = Wo;  dst = wo;  idx4 -= 3 * D_ * D_; }
        float4 v = *(const float4*)(src + idx4);
        *(__half2*)(dst + idx4)     = __floats2half2_rn(v.x, v.y);
        *(__half2*)(dst + idx4 + 2) = __floats2half2_rn(v.z, v.w);
        return;
    }

    {
        int r = bid - PREP_LN0;
        const bool is_q = (r < B_ * LQ_);
        const int  row  = is_q ? r : r - B_ * LQ_;
        const float* x  = is_q ? xq  : xkv;
        const float* w  = is_q ? nqw : nkw;
        const float* bb = is_q ? nqb : nkb;
        __half* y       = is_q ? yq  : ykv;

        const float* xr = x + (size_t)row * D_;
        float4 v = *(const float4*)(xr + tid * 4);
        float s  = v.x + v.y + v.z + v.w;
        float sq = v.x * v.x + v.y * v.y + v.z * v.z + v.w * v.w;
        #pragma unroll
        for (int o = 16; o; o >>= 1) {
            s  += __shfl_xor_sync(0xffffffffu, s,  o);
            sq += __shfl_xor_sync(0xffffffffu, sq, o);
        }
        __shared__ float ss[8], ssq[8];
        int wid = tid >> 5, ln = tid & 31;
        if (ln == 0) { ss[wid] = s; ssq[wid] = sq; }
        __syncthreads();
        if (tid == 0) {
            float S = 0.f, SQ = 0.f;
            #pragma unroll
            for (int i = 0; i < 8; i++) { S += ss[i]; SQ += ssq[i]; }
            float mu  = S * (1.0f / D_);
            float var = SQ * (1.0f / D_) - mu * mu;
            ss[0]  = mu;
            ssq[0] = rsqrtf(fmaxf(var, 0.0f) + 1e-5f);
        }
        __syncthreads();
        float mu = ss[0], inv = ssq[0];
        float4 wv = *(const float4*)(w  + tid * 4);
        float4 bv = *(const float4*)(bb + tid * 4);
        __half* yr = y + (size_t)row * D_ + tid * 4;
        *(__half2*)(yr)     = __floats2half2_rn((v.x - mu) * inv * wv.x + bv.x,
                                                (v.y - mu) * inv * wv.y + bv.y);
        *(__half2*)(yr + 2) = __floats2half2_rn((v.z - mu) * inv * wv.z + bv.z,
                                                (v.w - mu) * inv * wv.w + bv.w);
    }
}

// ========== per-head write helpers for GEMM epilogues ==========
__device__ __forceinline__ void write_q_pair(int mrow, int n, float2 v) {
    int b = mrow >> 10, qr = mrow & 1023, h = n >> 6, d = n & 63;
    __half* dst = g_q1 + ((size_t)((b * H_ + h) * LQ_ + qr)) * HD_ + d;
    *(__half2*)dst = __floats2half2_rn(v.x, v.y);
}
__device__ __forceinline__ void write_kv_pair(int mrow, int n, float2 v) {
    int b = mrow >> 11, kr = mrow & 2047;
    int h2 = n >> 6, d = n & 63;
    __half* dst = (h2 < H_)
        ? g_k1 + ((size_t)((b * H_ + h2) * LKV_ + kr)) * HD_ + d
        : g_v1 + ((size_t)((b * H_ + (h2 - H_)) * LKV_ + kr)) * HD_ + d;
    *(__half2*)dst = __floats2half2_rn(v.x, v.y);
}

// ========= fp16 warp-MMA GEMM body (BK=32, 4-stage ring, 2-ahead issue) =========
// C-tile = A[m0:+128,1024] @ W[n0:+128,1024]^T. 8 warps 32x64, BK=32, NK=32.
// MODE 0: fp32 C + bias + residual; MODE 1: Q per-head; MODE 2: KV per-head.
#define SSTRIDE 40                       // fp16 per smem row (80B)
#define GSTAGE_BYTES (128 * SSTRIDE * 2) // 10240 B per operand per stage
#define GSTAGES 4
#define GEMM_SMEM (2 * GSTAGES * GSTAGE_BYTES)  // 81920 B -> 2 CTAs/SM
#define NKG (D_ / 32)   // 32

template <int MODE>
__device__ __forceinline__ void gemm_body(
    const __half* __restrict__ A, const __half* __restrict__ W,
    const float* __restrict__ bias, const float* __restrict__ R,
    float* __restrict__ C, int N, int m0, int n0, char* gsm)
{
    const uint32_t smem_u = smem_to_u32(gsm);
    const uint32_t sa_u = smem_u;                        // A stages 0..3
    const uint32_t sb_u = smem_u + GSTAGES * GSTAGE_BYTES;

    const int tid  = threadIdx.x;
    const int lane = tid & 31;
    const int wid  = tid >> 5;
    const int warp_m = wid & 3;
    const int warp_n = wid >> 2;

    const int lr = tid >> 2;             // 0..63
    const int lu = tid & 3;              // 16B unit
    const __half* ag = A + (size_t)(m0 + lr) * D_ + lu * 8;
    const __half* bg = W + (size_t)(n0 + lr) * D_ + lu * 8;
    const uint32_t row_b  = (uint32_t)(lr * SSTRIDE * 2 + lu * 16);
    const uint32_t row_b2 = row_b + (uint32_t)(64 * SSTRIDE * 2);

    float acc[2][8][4];
    #pragma unroll
    for (int i = 0; i < 2; i++)
        #pragma unroll
        for (int j = 0; j < 8; j++)
            #pragma unroll
            for (int t = 0; t < 4; t++) acc[i][j][t] = 0.0f;

    const uint32_t a_off = (uint32_t)((warp_m * 32 + (lane & 15)) * SSTRIDE * 2
                                      + (lane >> 4) * 16);
    const uint32_t b_off = (uint32_t)((warp_n * 64 + ((lane >> 4) & 1) * 8 + (lane & 7)) * SSTRIDE * 2
                                      + ((lane >> 3) & 1) * 16);

    auto issue_stage = [&](int kt, int buf) {
        const size_t koff = (size_t)kt * 32;
        const uint32_t sa_s = sa_u + (uint32_t)(buf * GSTAGE_BYTES);
        const uint32_t sb_s = sb_u + (uint32_t)(buf * GSTAGE_BYTES);
        cp_async16(sa_s + row_b,  ag + koff);
        cp_async16(sa_s + row_b2, ag + (size_t)64 * D_ + koff);
        cp_async16(sb_s + row_b,  bg + koff);
        cp_async16(sb_s + row_b2, bg + (size_t)64 * D_ + koff);
    };

    // prologue: stages 0,1 (two groups)
    issue_stage(0, 0);
    CP_ASYNC_COMMIT();
    issue_stage(1, 1);
    CP_ASYNC_COMMIT();

    for (int kt = 0; kt < NKG; kt++) {
        // 2-ahead issue into 4-buffer ring.
        // WAR safe: passing iteration kt-1's barrier implies compute(kt-2) done,
        // and (kt+2)%4 == (kt-2)%4.
        if (kt + 2 < NKG) issue_stage(kt + 2, (kt + 2) & 3);
        CP_ASYNC_COMMIT();               // unconditional: keeps wait(2) exact
        CP_ASYNC_WAIT(2);                // stage kt has arrived
        __syncthreads();                 // single barrier per kt

        const int cur = kt & 3;
        const uint32_t sa_cur = sa_u + (uint32_t)(cur * GSTAGE_BYTES);
        const uint32_t sb_cur = sb_u + (uint32_t)(cur * GSTAGE_BYTES);
        #pragma unroll
        for (int ks = 0; ks < 2; ks++) {
            uint32_t a_frag[2][4];
            #pragma unroll
            for (int im = 0; im < 2; im++)
                ldmatrix_x4(a_frag[im], sa_cur + a_off
                            + (uint32_t)(im * 16 * SSTRIDE * 2 + ks * 32));
            uint32_t b_frag[4][4];
            #pragma unroll
            for (int iu = 0; iu < 4; iu++)
                ldmatrix_x4(b_frag[iu], sb_cur + b_off
                            + (uint32_t)(iu * 16 * SSTRIDE * 2 + ks * 32));
            #pragma unroll
            for (int im = 0; im < 2; im++)
                #pragma unroll
                for (int iu = 0; iu < 4; iu++) {
                    mma_16816(acc[im][iu * 2 + 0], a_frag[im], b_frag[iu][0], b_frag[iu][1]);
                    mma_16816(acc[im][iu * 2 + 1], a_frag[im], b_frag[iu][2], b_frag[iu][3]);
                }
        }
    }

    const int gr = lane >> 2;
    const int gc = (lane & 3) * 2;
    #pragma unroll
    for (int im = 0; im < 2; im++) {
        const int mrow = m0 + warp_m * 32 + im * 16 + gr;
        #pragma unroll
        for (int in = 0; in < 8; in++) {
            const int n = n0 + warp_n * 64 + in * 8 + gc;
            float b0 = bias[n], b1 = bias[n + 1];
            float2 v0 = make_float2(acc[im][in][0] + b0, acc[im][in][1] + b1);
            float2 v1 = make_float2(acc[im][in][2] + b0, acc[im][in][3] + b1);
            if (MODE == 0) {
                float2 r0 = *(const float2*)(R + (size_t)mrow * N + n);
                float2 r1 = *(const float2*)(R + (size_t)(mrow + 8) * N + n);
                v0.x += r0.x; v0.y += r0.y;
                v1.x += r1.x; v1.y += r1.y;
                *(float2*)(C + (size_t)mrow * N + n)       = v0;
                *(float2*)(C + (size_t)(mrow + 8) * N + n) = v1;
            } else if (MODE == 1) {
                write_q_pair(mrow,     n, v0);
                write_q_pair(mrow + 8, n, v1);
            } else {
                write_kv_pair(mrow,     n, v0);
                write_kv_pair(mrow + 8, n, v1);
            }
        }
    }
}

// fused Q+KV projection: blocks [0,1024) = KV tiles, [1024,1280) = Q tiles.
__global__ void __launch_bounds__(256, 2) proj_qkv_kernel(
    const __half* __restrict__ qk, const __half* __restrict__ kvk,
    const __half* __restrict__ wq, const __half* __restrict__ wkv,
    const float* __restrict__ bq, const float* __restrict__ bkv)
{
    extern __shared__ char gsm[];
    const int bid = blockIdx.x;
    if (bid < 1024) {
        const int m0 = (bid >> 4) * 128, n0 = (bid & 15) * 128;
        const int b = m0 >> 11, kr0 = m0 & 2047;
        if (kr0 >= g_len[b]) return;   // attention never reads these kv rows
        gemm_body<2>(kvk, wkv, bkv, nullptr, nullptr, 2 * D_, m0, n0, gsm);
    } else {
        const int r = bid - 1024;
        const int m0 = (r >> 3) * 128, n0 = (r & 7) * 128;
        gemm_body<1>(qk, wq, bq, nullptr, nullptr, D_, m0, n0, gsm);
    }
}

// O projection + residual
__global__ void __launch_bounds__(256, 2) proj_o_kernel(
    const __half* __restrict__ ak, const __half* __restrict__ wo,
    const float* __restrict__ bo, const float* __restrict__ R,
    float* __restrict__ out)
{
    extern __shared__ char gsm[];
    const int bid = blockIdx.x;
    const int m0 = (bid >> 3) * 128, n0 = (bid & 7) * 128;
    gemm_body<0>(ak, wo, bo, R, out, D_, m0, n0, gsm);
}

// ================= fp16 HMMA flash attention (R14 version, unchanged) =================
#define AQ  128
#define SQ  72     // smem row stride in fp16 (144B)
#define KTILE 4608             // 64 * SQ (halfs)
#define FA_SMEM_BYTES ((27648 + 9216) * 2)   // 73728

__global__ void __launch_bounds__(256, 2) flash_attn_mma_kernel(
    const __half* __restrict__ q1, const __half* __restrict__ k1,
    const __half* __restrict__ v1, __half* __restrict__ outk)
{
    extern __shared__ __half smem_h[];
    __half* Qs = smem_h + 27648;

    const int b = blockIdx.z, h = blockIdx.y, qt = blockIdx.x;
    const int tid = threadIdx.x, lane = tid & 31, wid = tid >> 5;
    const int gr = lane >> 2, gc = (lane & 3) * 2;

    const uint32_t smem_u = smem_to_u32(smem_h);
    const uint32_t ks_u = smem_u;
    const uint32_t vs_u = smem_u + 3 * KTILE * 2;
    const uint32_t qs_u = smem_u + 27648 * 2;

    const __half* qg = q1 + ((size_t)((b * H_ + h) * LQ_ + qt * AQ)) * HD_;
    #pragma unroll
    for (int rep = 0; rep < 4; rep++) {
        int idx = rep * 256 + tid;
        int r = idx >> 3, u = idx & 7;
        *(uint4*)&Qs[r * SQ + u * 8] = *(const uint4*)(qg + (size_t)r * HD_ + u * 8);
    }
    __syncthreads();

    uint32_t qfrag[4][4];
    const uint32_t a_base = qs_u + (uint32_t)((wid * 16 + (lane & 15)) * SQ * 2
                                              + (lane >> 4) * 16);
    #pragma unroll
    for (int ks = 0; ks < 4; ks++)
        ldmatrix_x4(qfrag[ks], a_base + (uint32_t)(ks * 32));

    const uint32_t kb_off = (uint32_t)((((lane >> 4) & 1) * 8 + (lane & 7)) * SQ * 2
                                       + ((lane >> 3) & 1) * 16);
    const uint32_t vb_off = (uint32_t)(((lane & 7) + ((lane >> 3) & 1) * 8) * SQ * 2
                                       + (lane >> 4) * 16);

    const int len   = g_len[b];
    const int ntile = (len + 63) >> 6;

    const __half* kbase = k1 + ((size_t)((b * H_ + h) * LKV_)) * HD_;
    const __half* vbase = v1 + ((size_t)((b * H_ + h) * LKV_)) * HD_;

    auto issue_tile = [&](int kt, int buf) {
        const __half* kg = kbase + (size_t)(kt * 64) * HD_;
        const __half* vg = vbase + (size_t)(kt * 64) * HD_;
        const uint32_t kdst = ks_u + (uint32_t)(buf * KTILE * 2);
        const uint32_t vdst = vs_u + (uint32_t)(buf * KTILE * 2);
        #pragma unroll
        for (int rep = 0; rep < 2; rep++) {
            int idx = rep * 256 + tid;
            int r = idx >> 3, u = idx & 7;
            uint32_t off = (uint32_t)((r * SQ + u * 8) * 2);
            cp_async16(kdst + off, kg + (size_t)r * HD_ + u * 8);
            cp_async16(vdst + off, vg + (size_t)r * HD_ + u * 8);
        }
    };

    float m_r[2] = {-1e30f, -1e30f};
    float l_r[2] = {0.0f, 0.0f};
    float acc_o[8][4];
    #pragma unroll
    for (int i = 0; i < 8; i++)
        #pragma unroll
        for (int j = 0; j < 4; j++) acc_o[i][j] = 0.0f;

    issue_tile(0, 0);
    CP_ASYNC_COMMIT();

    for (int kt = 0; kt < ntile; kt++) {
        const int buf = kt % 3;
        if (kt + 1 < ntile) issue_tile(kt + 1, (kt + 1) % 3);
        CP_ASYNC_COMMIT();
        CP_ASYNC_WAIT(1);
        __syncthreads();

        const uint32_t kcur = ks_u + (uint32_t)(buf * KTILE * 2);
        const uint32_t vcur = vs_u + (uint32_t)(buf * KTILE * 2);

        float acc_s[8][4];
        #pragma unroll
        for (int i = 0; i < 8; i++)
            #pragma unroll
            for (int j = 0; j < 4; j++) acc_s[i][j] = 0.0f;

        #pragma unroll
        for (int ks = 0; ks < 4; ks++) {
            uint32_t bf[4][4];
            #pragma unroll
            for (int nt4 = 0; nt4 < 4; nt4++)
                ldmatrix_x4(bf[nt4], kcur + kb_off
                            + (uint32_t)(nt4 * 16 * SQ * 2 + ks * 32));
            #pragma unroll
            for (int nt4 = 0; nt4 < 4; nt4++) {
                mma_16816(acc_s[nt4 * 2 + 0], qfrag[ks], bf[nt4][0], bf[nt4][1]);
                mma_16816(acc_s[nt4 * 2 + 1], qfrag[ks], bf[nt4][2], bf[nt4][3]);
            }
        }

        const int rem = len - kt * 64;
        #pragma unroll
        for (int nt = 0; nt < 8; nt++) {
            int c0 = nt * 8 + gc;
            bool k0 = (c0 >= rem), k1m = (c0 + 1 >= rem);
            acc_s[nt][0] = k0  ? -1e9f : acc_s[nt][0] * 0.125f;
            acc_s[nt][1] = k1m ? -1e9f : acc_s[nt][1] * 0.125f;
            acc_s[nt][2] = k0  ? -1e9f : acc_s[nt][2] * 0.125f;
            acc_s[nt][3] = k1m ? -1e9f : acc_s[nt][3] * 0.125f;
        }

        float tmax0 = -1e30f, tmax1 = -1e30f;
        #pragma unroll
        for (int nt = 0; nt < 8; nt++) {
            tmax0 = fmaxf(tmax0, fmaxf(acc_s[nt][0], acc_s[nt][1]));
            tmax1 = fmaxf(tmax1, fmaxf(acc_s[nt][2], acc_s[nt][3]));
        }
        #pragma unroll
        for (int o = 1; o < 4; o <<= 1) {
            tmax0 = fmaxf(tmax0, __shfl_xor_sync(0xffffffffu, tmax0, o));
            tmax1 = fmaxf(tmax1, __shfl_xor_sync(0xffffffffu, tmax1, o));
        }
        float mn0 = fmaxf(m_r[0], tmax0), mn1 = fmaxf(m_r[1], tmax1);
        float al0 = __expf(m_r[0] - mn0), al1 = __expf(m_r[1] - mn1);
        float rs0 = 0.0f, rs1 = 0.0f;
        #pragma unroll
        for (int nt = 0; nt < 8; nt++) {
            acc_s[nt][0] = __expf(acc_s[nt][0] - mn0);
            acc_s[nt][1] = __expf(acc_s[nt][1] - mn0);
            acc_s[nt][2] = __expf(acc_s[nt][2] - mn1);
            acc_s[nt][3] = __expf(acc_s[nt][3] - mn1);
            rs0 += acc_s[nt][0] + acc_s[nt][1];
            rs1 += acc_s[nt][2] + acc_s[nt][3];
        }
        #pragma unroll
        for (int o = 1; o < 4; o <<= 1) {
            rs0 += __shfl_xor_sync(0xffffffffu, rs0, o);
            rs1 += __shfl_xor_sync(0xffffffffu, rs1, o);
        }
        l_r[0] = l_r[0] * al0 + rs0;  m_r[0] = mn0;
        l_r[1] = l_r[1] * al1 + rs1;  m_r[1] = mn1;
        #pragma unroll
        for (int nt = 0; nt < 8; nt++) {
            acc_o[nt][0] *= al0; acc_o[nt][1] *= al0;
            acc_o[nt][2] *= al1; acc_o[nt][3] *= al1;
        }

        #pragma unroll
        for (int ks4 = 0; ks4 < 4; ks4++) {
            uint32_t af[4];
            __half2 t0 = __floats2half2_rn(acc_s[2 * ks4][0],     acc_s[2 * ks4][1]);
            __half2 t1 = __floats2half2_rn(acc_s[2 * ks4][2],     acc_s[2 * ks4][3]);
            __half2 t2 = __floats2half2_rn(acc_s[2 * ks4 + 1][0], acc_s[2 * ks4 + 1][1]);
            __half2 t3 = __floats2half2_rn(acc_s[2 * ks4 + 1][2], acc_s[2 * ks4 + 1][3]);
            af[0] = *(uint32_t*)&t0;
            af[1] = *(uint32_t*)&t1;
            af[2] = *(uint32_t*)&t2;
            af[3] = *(uint32_t*)&t3;
            uint32_t bf[4][4];
            #pragma unroll
            for (int g = 0; g < 4; g++)
                ldmatrix_x4_trans(bf[g], vcur + vb_off
                                  + (uint32_t)(ks4 * 16 * SQ * 2 + g * 32));
            #pragma unroll
            for (int g = 0; g < 4; g++) {
                mma_16816(acc_o[g * 2 + 0], af, bf[g][0], bf[g][1]);
                mma_16816(acc_o[g * 2 + 1], af, bf[g][2], bf[g][3]);
            }
        }
    }

    float inv0 = 1.0f / l_r[0], inv1 = 1.0f / l_r[1];
    const int qrow0 = qt * AQ + wid * 16 + gr;
    __half* p0 = outk + ((size_t)(b * LQ_ + qrow0)) * D_ + h * HD_;
    __half* p1 = p0 + (size_t)8 * D_;
    #pragma unroll
    for (int nt = 0; nt < 8; nt++) {
        int col = nt * 8 + gc;
        *(__half2*)(p0 + col) = __floats2half2_rn(acc_o[nt][0] * inv0,
                                                  acc_o[nt][1] * inv0);
        *(__half2*)(p1 + col) = __floats2half2_rn(acc_o[nt][2] * inv1,
                                                  acc_o[nt][3] * inv1);
    }
}

// ================= host launcher =================
extern "C" void kernel_launch(void* const* d_in, const int* in_sizes, int n_in,
                              void* d_out, int out_size) {
    const float*         q    = (const float*)d_in[0];
    const float*         kv   = (const float*)d_in[1];
    const unsigned char* mask = (const unsigned char*)d_in[2];
    const float*         nqw  = (const float*)d_in[3];
    const float*         nqb  = (const float*)d_in[4];
    const float*         nkw  = (const float*)d_in[5];
    const float*         nkb  = (const float*)d_in[6];
    const float*         Wq   = (const float*)d_in[7];
    const float*         bq   = (const float*)d_in[8];
    const float*         Wkv  = (const float*)d_in[9];
    const float*         bkv  = (const float*)d_in[10];
    const float*         Wo   = (const float*)d_in[11];
    const float*         bo   = (const float*)d_in[12];
    float* out = (float*)d_out;

    __half *qk, *kvk, *ak, *wq, *wkv, *wo, *q1, *k1, *v1;
    cudaGetSymbolAddress((void**)&qk,  g_qk);
    cudaGetSymbolAddress((void**)&kvk, g_kvk);
    cudaGetSymbolAddress((void**)&ak,  g_ak);
    cudaGetSymbolAddress((void**)&wq,  g_wq);
    cudaGetSymbolAddress((void**)&wkv, g_wkv);
    cudaGetSymbolAddress((void**)&wo,  g_wo);
    cudaGetSymbolAddress((void**)&q1,  g_q1);
    cudaGetSymbolAddress((void**)&k1,  g_k1);
    cudaGetSymbolAddress((void**)&v1,  g_v1);

    cudaFuncSetAttribute(flash_attn_mma_kernel,
                         cudaFuncAttributeMaxDynamicSharedMemorySize, FA_SMEM_BYTES);
    cudaFuncSetAttribute(proj_qkv_kernel,
                         cudaFuncAttributeMaxDynamicSharedMemorySize, GEMM_SMEM);
    cudaFuncSetAttribute(proj_o_kernel,
                         cudaFuncAttributeMaxDynamicSharedMemorySize, GEMM_SMEM);

    prep_kernel<<<PREP_BLOCKS, 256>>>(mask, Wq, Wkv, Wo, wq, wkv, wo,
                                      q, kv, nqw, nqb, nkw, nkb, qk, kvk); // 0

    proj_qkv_kernel<<<1280, 256, GEMM_SMEM>>>(qk, kvk, wq, wkv, bq, bkv);  // 1

    flash_attn_mma_kernel<<<dim3(LQ_ / AQ, H_, B_), 256, FA_SMEM_BYTES>>>(
        q1, k1, v1, ak);                                                    // 2

    proj_o_kernel<<<256, 256, GEMM_SMEM>>>(ak, wo, bo, q, out);             // 3
}